// round 17
// baseline (speedup 1.0000x reference)
#include <cuda_runtime.h>
#include <math.h>

#define N_FFT   1024
#define HOP     256
#define NBINS   513
#define NMELS   128
#define BATCH   32
#define SIGLEN  160000
#define PAD     512
#define NFRAMES 626
#define NPAIRS  313
#define NBLK    79
#define SUP     26

#define KCH     32
#define LCH     20
#define LCH_LAST (NFRAMES - (KCH - 1) * LCH)   // 6
#define EMA_A   0.975f
#define EMA_S   0.025f

#define PADI(i) ((i) + ((i) >> 4))
#define FSZ2    1088

#define UNIT_BAR(q) asm volatile("bar.sync %0, %1;" :: "r"((q) + 1), "r"(64) : "memory")

// ---------------- device scratch ----------------
__device__ float  g_mel[BATCH * NFRAMES * NMELS];
__device__ float  g_T  [BATCH * KCH * NMELS];
__device__ int    g_cnt[BATCH];
__device__ float  g_fbT[SUP * NMELS];
__device__ int    g_start[NMELS];
__device__ int    g_len[NMELS];
__device__ float2 g_tw[256];

// ---------------- prep ----------------
__global__ void prep_kernel(const float* __restrict__ fb) {
    const int m    = blockIdx.x;
    const int lane = threadIdx.x;

    if (m < 8) {
        int k = m * 32 + lane;
        float ang = -6.283185307179586f * (float)k / (float)N_FFT;
        float s, c;
        sincosf(ang, &s, &c);
        g_tw[k] = make_float2(c, s);
    }
    if (m < BATCH && lane == 0) g_cnt[m] = 0;   // reset barrier counters

    int first = 0x7fffffff, last = -1;
    for (int f = lane; f < NBINS; f += 32) {
        float v = fb[f * NMELS + m];
        if (v != 0.0f) { first = min(first, f); last = max(last, f); }
    }
    first = __reduce_min_sync(0xffffffffu, first);
    last  = __reduce_max_sync(0xffffffffu, last);

    int st  = (last < 0) ? 0 : first;
    int len = (last < 0) ? 0 : (last - first + 1);
    if (len > SUP) len = SUP;

    if (lane == 0) { g_start[m] = st; g_len[m] = len; }
    if (lane < SUP) {
        int j = lane;
        g_fbT[j * NMELS + m] = (j < len) ? fb[(st + j) * NMELS + m] : 0.0f;
    }
}

__device__ __forceinline__ int reflect_idx(int src) {
    if (src < 0) src = -src;
    if (src >= SIGLEN) src = 2 * SIGLEN - 2 - src;
    return src;
}

__device__ __forceinline__ int rev8(int v) {
    int r = __brev(v) >> 24;
    return ((r & 0x55) << 1) | ((r & 0xAA) >> 1);
}

// ---------------- f32x2 packed complex primitives (sm_103a) --------------
__device__ __forceinline__ float2 f2add(float2 a, float2 b) {
    float2 r;
    asm("{.reg .b64 x,y,z;\n\t"
        "mov.b64 x,{%2,%3};\n\t"
        "mov.b64 y,{%4,%5};\n\t"
        "add.rn.f32x2 z,x,y;\n\t"
        "mov.b64 {%0,%1},z;}"
        : "=f"(r.x), "=f"(r.y)
        : "f"(a.x), "f"(a.y), "f"(b.x), "f"(b.y));
    return r;
}
__device__ __forceinline__ float2 f2sub(float2 a, float2 b) {
    float2 r;
    asm("{.reg .b64 x,y,z;\n\t"
        "mov.b64 x,{%2,%3};\n\t"
        "mov.b64 y,{%4,%5};\n\t"
        "sub.rn.f32x2 z,x,y;\n\t"
        "mov.b64 {%0,%1},z;}"
        : "=f"(r.x), "=f"(r.y)
        : "f"(a.x), "f"(a.y), "f"(b.x), "f"(b.y));
    return r;
}
__device__ __forceinline__ float2 f2cmul(float2 v, float2 w, float2 wn) {
    float2 r;
    asm("{.reg .b64 a,b,c,d;\n\t"
        "mov.b64 a,{%2,%2};\n\t"
        "mov.b64 b,{%4,%5};\n\t"
        "mov.b64 c,{%3,%3};\n\t"
        "mov.b64 d,{%6,%7};\n\t"
        "mul.rn.f32x2 c,c,d;\n\t"
        "fma.rn.f32x2 a,a,b,c;\n\t"
        "mov.b64 {%0,%1},a;}"
        : "=f"(r.x), "=f"(r.y)
        : "f"(v.x), "f"(v.y), "f"(w.x), "f"(w.y), "f"(wn.x), "f"(wn.y));
    return r;
}

#define R4BFLY2(A,B,C,D, Y0,Y1,Y2,Y3)                                    \
    {                                                                     \
        float2 T0 = f2add(A, C), T1 = f2sub(A, C);                        \
        float2 T2 = f2add(B, D), T3 = f2sub(B, D);                        \
        float2 T3s = make_float2(T3.y, -T3.x);                            \
        Y0 = f2add(T0, T2);  Y2 = f2sub(T0, T2);                          \
        Y1 = f2add(T1, T3s); Y3 = f2sub(T1, T3s);                         \
    }

#define TWSET(w1, w2, w3)                                                 \
    float2 w2 = make_float2(w1.x*w1.x - w1.y*w1.y, 2.0f*w1.x*w1.y);       \
    float2 w3 = make_float2(w1.x*w2.x - w1.y*w2.y, w1.x*w2.y + w1.y*w2.x);
#define NEGSWAP(w) make_float2(-(w).y, (w).x)

__device__ __forceinline__ float2 packmag(float2 Z1, float2 Z2) {
    float ar = 0.5f * (Z1.x + Z2.x);
    float ai = 0.5f * (Z1.y - Z2.y);
    float br = 0.5f * (Z1.y + Z2.y);
    float bi = 0.5f * (Z2.x - Z1.x);
    return make_float2(sqrtf(ar * ar + ai * ai), sqrtf(br * br + bi * bi));
}

// ---------------- fft + mel (unchanged from R16) --------------------------
__global__ __launch_bounds__(256, 4)
void fft_mel_kernel(const float* __restrict__ x) {
    __shared__ float2 cv[4 * FSZ2];

    const int tid = threadIdx.x;
    const int q   = tid >> 6;
    const int t   = tid & 63;
    const int b   = blockIdx.y;
    const int p0  = blockIdx.x * 4 + q;
    const int pr  = min(p0, NPAIRS - 1);

    const float* xb = x + (size_t)b * SIGLEN;
    float2* mcv = cv + q * FSZ2;

    const int baseA = 2 * pr * HOP - PAD;
    const int baseB = baseA + HOP;
    float2 xv[4][4];
    if (pr >= 1 && pr <= 310) {
        #pragma unroll
        for (int a = 0; a < 4; a++)
            #pragma unroll
            for (int bb = 0; bb < 4; bb++) {
                int n = t + 64 * bb + 256 * a;
                xv[a][bb] = make_float2(xb[baseA + n], xb[baseB + n]);
            }
    } else {
        #pragma unroll
        for (int a = 0; a < 4; a++)
            #pragma unroll
            for (int bb = 0; bb < 4; bb++) {
                int n = t + 64 * bb + 256 * a;
                xv[a][bb] = make_float2(xb[reflect_idx(baseA + n)],
                                        xb[reflect_idx(baseB + n)]);
            }
    }

    #pragma unroll
    for (int bb = 0; bb < 4; bb++) {
        float2 y0, y1, y2, y3;
        R4BFLY2(xv[0][bb], xv[1][bb], xv[2][bb], xv[3][bb], y0, y1, y2, y3);
        float2 w1 = __ldg(&g_tw[t + 64 * bb]);
        TWSET(w1, w2, w3);
        xv[0][bb] = y0;
        xv[1][bb] = f2cmul(y1, w1, NEGSWAP(w1));
        xv[2][bb] = f2cmul(y2, w2, NEGSWAP(w2));
        xv[3][bb] = f2cmul(y3, w3, NEGSWAP(w3));
    }
    {
        float2 w1 = __ldg(&g_tw[4 * t]);
        TWSET(w1, w2, w3);
        float2 w1n = NEGSWAP(w1), w2n = NEGSWAP(w2), w3n = NEGSWAP(w3);
        #pragma unroll
        for (int a = 0; a < 4; a++) {
            float2 y0, y1, y2, y3;
            R4BFLY2(xv[a][0], xv[a][1], xv[a][2], xv[a][3], y0, y1, y2, y3);
            xv[a][0] = y0;
            xv[a][1] = f2cmul(y1, w1, w1n);
            xv[a][2] = f2cmul(y2, w2, w2n);
            xv[a][3] = f2cmul(y3, w3, w3n);
        }
    }
    #pragma unroll
    for (int a = 0; a < 4; a++)
        #pragma unroll
        for (int bb = 0; bb < 4; bb++)
            mcv[PADI(t + 64 * bb + 256 * a)] = xv[a][bb];
    UNIT_BAR(q);

    {
        const int d4 = t >> 4, d3 = (t >> 2) & 3, d0 = t & 3;
        const int base = 256 * d4 + 64 * d3 + d0;
        #pragma unroll
        for (int c = 0; c < 4; c++)
            #pragma unroll
            for (int d = 0; d < 4; d++)
                xv[c][d] = mcv[PADI(base + 16 * c + 4 * d)];
        #pragma unroll
        for (int d = 0; d < 4; d++) {
            float2 y0, y1, y2, y3;
            R4BFLY2(xv[0][d], xv[1][d], xv[2][d], xv[3][d], y0, y1, y2, y3);
            float2 w1 = __ldg(&g_tw[16 * (d0 + 4 * d)]);
            TWSET(w1, w2, w3);
            xv[0][d] = y0;
            xv[1][d] = f2cmul(y1, w1, NEGSWAP(w1));
            xv[2][d] = f2cmul(y2, w2, NEGSWAP(w2));
            xv[3][d] = f2cmul(y3, w3, NEGSWAP(w3));
        }
        {
            float2 w1 = __ldg(&g_tw[64 * d0]);
            TWSET(w1, w2, w3);
            float2 w1n = NEGSWAP(w1), w2n = NEGSWAP(w2), w3n = NEGSWAP(w3);
            #pragma unroll
            for (int c = 0; c < 4; c++) {
                float2 y0, y1, y2, y3;
                R4BFLY2(xv[c][0], xv[c][1], xv[c][2], xv[c][3], y0, y1, y2, y3);
                xv[c][0] = y0;
                xv[c][1] = f2cmul(y1, w1, w1n);
                xv[c][2] = f2cmul(y2, w2, w2n);
                xv[c][3] = f2cmul(y3, w3, w3n);
            }
        }
        #pragma unroll
        for (int c = 0; c < 4; c++)
            #pragma unroll
            for (int d = 0; d < 4; d++)
                mcv[PADI(base + 16 * c + 4 * d)] = xv[c][d];
    }
    UNIT_BAR(q);

    const int m_pf   = tid & (NMELS - 1);
    const int st_pf  = g_start[m_pf];
    const int len_pf = g_len[m_pf];

    float2 mag1[4], mag2[4], mag0[3];
    const int v1 = t + 1, v2 = t + 65;
    #pragma unroll
    for (int task = 0; task < 2; task++) {
        const int v  = task ? v2 : v1;
        const int u  = rev8(v & 255);
        const int u2 = rev8((256 - v) & 255);
        float2 a0 = mcv[PADI(4*u)],   a1 = mcv[PADI(4*u+1)];
        float2 a2 = mcv[PADI(4*u+2)], a3 = mcv[PADI(4*u+3)];
        float2 G0, G1, G2, G3;
        R4BFLY2(a0, a1, a2, a3, G0, G1, G2, G3);
        float2 b0 = mcv[PADI(4*u2)],   b1 = mcv[PADI(4*u2+1)];
        float2 b2 = mcv[PADI(4*u2+2)], b3 = mcv[PADI(4*u2+3)];
        float2 H0, H1, H2, H3;
        R4BFLY2(b0, b1, b2, b3, H0, H1, H2, H3);
        float2* mg = task ? mag2 : mag1;
        mg[0] = packmag(G0, H3);
        mg[1] = packmag(H0, G3);
        mg[2] = packmag(G1, H2);
        mg[3] = packmag(H1, G2);
    }
    if (t == 0) {
        float2 a0 = mcv[PADI(0)], a1 = mcv[PADI(1)];
        float2 a2 = mcv[PADI(2)], a3 = mcv[PADI(3)];
        float2 G0, G1, G2, G3;
        R4BFLY2(a0, a1, a2, a3, G0, G1, G2, G3);
        mag0[0] = packmag(G0, G0);
        mag0[1] = packmag(G1, G3);
        mag0[2] = packmag(G2, G2);
    }
    UNIT_BAR(q);

    {
        float2* sq = cv + q * FSZ2;
        sq[v1]       = mag1[0];
        sq[256 - v1] = mag1[1];
        sq[256 + v1] = mag1[2];
        sq[512 - v1] = mag1[3];
        sq[v2]       = mag2[0];
        sq[256 - v2] = mag2[1];
        sq[256 + v2] = mag2[2];
        sq[512 - v2] = mag2[3];
        if (t == 0) { sq[0] = mag0[0]; sq[256] = mag0[1]; sq[512] = mag0[2]; }
        if (t < SUP) sq[NBINS + t] = make_float2(0.0f, 0.0f);
    }
    __syncthreads();

    {
        const int m   = m_pf;
        const int h   = tid >> 7;
        const int st  = st_pf;
        const int len = len_pf;
        const float2* s0 = cv + (2 * h)     * FSZ2 + st;
        const float2* s1 = cv + (2 * h + 1) * FSZ2 + st;
        float a0 = 0.0f, b0 = 0.0f, a1 = 0.0f, b1 = 0.0f;
        #pragma unroll 2
        for (int j = 0; j < len; j++) {
            float fv = g_fbT[j * NMELS + m];
            float2 v0 = s0[j], v1f = s1[j];
            a0 = fmaf(v0.x,  fv, a0);  b0 = fmaf(v0.y,  fv, b0);
            a1 = fmaf(v1f.x, fv, a1);  b1 = fmaf(v1f.y, fv, b1);
        }
        const int pbase = blockIdx.x * 4;
        int fr0 = 2 * (pbase + 2 * h);
        int fr1 = 2 * (pbase + 2 * h + 1);
        size_t rowb = (size_t)b * NFRAMES;
        if (fr0 < NFRAMES)     g_mel[(rowb + fr0)     * NMELS + m] = a0;
        if (fr0 + 1 < NFRAMES) g_mel[(rowb + fr0 + 1) * NMELS + m] = b0;
        if (fr1 < NFRAMES)     g_mel[(rowb + fr1)     * NMELS + m] = a1;
        if (fr1 + 1 < NFRAMES) g_mel[(rowb + fr1 + 1) * NMELS + m] = b1;
    }
}

// ---------------- PCEN fused: T + grid-barrier + outputs -----------------
__device__ __forceinline__ float pcen_f(float v, float M) {
    float pw = exp2f(-0.98f * __log2f(M + 1e-6f));
    float y  = fmaf(v, pw, 2.0f);
    return y * rsqrtf(y) - 1.41421356237309515f;
}

__global__ __launch_bounds__(128, 8)
void pcen_fused_kernel(float* __restrict__ out) {
    const int m = threadIdx.x;
    const int b = blockIdx.x;
    const int c = blockIdx.y;

    const int t0 = c * LCH;
    const int nt = (c == KCH - 1) ? LCH_LAST : LCH;
    const float* p = g_mel + ((size_t)b * NFRAMES + t0) * NMELS + m;
    float*       o = out  + ((size_t)b * NFRAMES + t0) * NMELS + m;

    // load chunk into registers (single g_mel read)
    float v[LCH];
    #pragma unroll
    for (int t = 0; t < LCH; t++)
        if (t < nt) v[t] = p[(size_t)t * NMELS];

    // partial T (zero incoming state; chunk 0 seeds with v0)
    if (c < KCH - 1) {
        float T;
        if (c == 0) {
            T = v[0];
            #pragma unroll
            for (int t = 1; t < LCH; t++) T = fmaf(EMA_A, T, EMA_S * v[t]);
        } else {
            T = 0.0f;
            #pragma unroll
            for (int t = 0; t < LCH; t++) T = fmaf(EMA_A, T, EMA_S * v[t]);
        }
        g_T[((size_t)b * KCH + c) * NMELS + m] = T;
        __threadfence();
    }
    __syncthreads();
    if (threadIdx.x == 0 && c < KCH - 1)
        atomicAdd(&g_cnt[b], 1);

    float state;
    if (c == 0) {
        state = v[0];
        o[0] = pcen_f(v[0], state);
        #pragma unroll
        for (int t = 1; t < LCH; t++) {
            state = fmaf(EMA_A, state, EMA_S * v[t]);
            o[(size_t)t * NMELS] = pcen_f(v[t], state);
        }
        return;
    }

    // wait for all 31 T-writers of this batch
    if (threadIdx.x == 0) {
        int cnt;
        do {
            asm volatile("ld.global.cg.s32 %0, [%1];"
                         : "=r"(cnt) : "l"(&g_cnt[b]) : "memory");
            if (cnt < KCH - 1) __nanosleep(100);
        } while (cnt < KCH - 1);
    }
    __syncthreads();
    __threadfence();   // acquire: make g_T writes visible

    // prefix over g_T[0..c-1]
    float A = 1.0f;
    #pragma unroll
    for (int i = 0; i < LCH; i++) A *= EMA_A;
    state = 0.0f;
    const float* Tp = g_T + (size_t)b * KCH * NMELS + m;
    {
        float A4 = (A * A) * (A * A);
        int cc = 0;
        for (; cc + 4 <= c; cc += 4) {
            float t0v = Tp[(size_t)(cc)     * NMELS];
            float t1v = Tp[(size_t)(cc + 1) * NMELS];
            float t2v = Tp[(size_t)(cc + 2) * NMELS];
            float t3v = Tp[(size_t)(cc + 3) * NMELS];
            float s = fmaf(A, t0v, t1v);
            s = fmaf(A, s, t2v);
            s = fmaf(A, s, t3v);
            state = fmaf(A4, state, s);
        }
        for (; cc < c; cc++)
            state = fmaf(A, state, Tp[(size_t)cc * NMELS]);
    }

    if (c < KCH - 1) {
        #pragma unroll
        for (int t = 0; t < LCH; t++) {
            state = fmaf(EMA_A, state, EMA_S * v[t]);
            o[(size_t)t * NMELS] = pcen_f(v[t], state);
        }
    } else {
        #pragma unroll
        for (int t = 0; t < LCH_LAST; t++) {
            state = fmaf(EMA_A, state, EMA_S * v[t]);
            o[(size_t)t * NMELS] = pcen_f(v[t], state);
        }
    }
}

// ---------------- launch ----------------
extern "C" void kernel_launch(void* const* d_in, const int* in_sizes, int n_in,
                              void* d_out, int out_size) {
    const float* x  = (const float*)d_in[0];   // (32, 160000) f32
    const float* fb = (const float*)d_in[1];   // (513, 128)  f32
    float* out = (float*)d_out;                // (32, 626, 128) f32

    prep_kernel<<<NMELS, 32>>>(fb);
    fft_mel_kernel<<<dim3(NBLK, BATCH), 256>>>(x);
    pcen_fused_kernel<<<dim3(BATCH, KCH), 128>>>(out);
}